// round 4
// baseline (speedup 1.0000x reference)
#include <cuda_runtime.h>
#include <cuda_bf16.h>
#include <math.h>
#include <stdint.h>

// Problem constants
#define BSZ   2
#define SEQ   1024
#define DMODEL 4096
#define NH    32
#define NKVH  8
#define HD    128
#define MROWS (BSZ * SEQ)      // 2048
#define QCOLS (NH * HD)        // 4096
#define KCOLS (NKVH * HD)      // 1024

// ---------------------------------------------------------------------------
// Device-global scratch (no allocations allowed)
// ---------------------------------------------------------------------------
__device__ float g_Q [(size_t)MROWS * QCOLS];
__device__ float g_K [(size_t)MROWS * KCOLS];
__device__ float g_V [(size_t)MROWS * KCOLS];

// bf16 split operands (hi/lo) — activations [M][K], weights transposed [N][K]
__device__ __align__(16) unsigned short g_xh [(size_t)MROWS * DMODEL];
__device__ __align__(16) unsigned short g_xl [(size_t)MROWS * DMODEL];
__device__ __align__(16) unsigned short g_AOh[(size_t)MROWS * QCOLS];
__device__ __align__(16) unsigned short g_AOl[(size_t)MROWS * QCOLS];
__device__ __align__(16) unsigned short g_Wqh[(size_t)QCOLS * DMODEL];
__device__ __align__(16) unsigned short g_Wql[(size_t)QCOLS * DMODEL];
__device__ __align__(16) unsigned short g_Wkh[(size_t)KCOLS * DMODEL];
__device__ __align__(16) unsigned short g_Wkl[(size_t)KCOLS * DMODEL];
__device__ __align__(16) unsigned short g_Wvh[(size_t)KCOLS * DMODEL];
__device__ __align__(16) unsigned short g_Wvl[(size_t)KCOLS * DMODEL];
__device__ __align__(16) unsigned short g_Woh[(size_t)DMODEL * QCOLS];
__device__ __align__(16) unsigned short g_Wol[(size_t)DMODEL * QCOLS];

// ---------------------------------------------------------------------------
// helpers
// ---------------------------------------------------------------------------
__device__ __forceinline__ uint32_t sptr(const void* p) {
    return (uint32_t)__cvta_generic_to_shared(p);
}
__device__ __forceinline__ void ldm4(uint32_t r[4], uint32_t addr) {
    asm volatile("ldmatrix.sync.aligned.m8n8.x4.shared.b16 {%0,%1,%2,%3}, [%4];"
                 : "=r"(r[0]), "=r"(r[1]), "=r"(r[2]), "=r"(r[3]) : "r"(addr));
}
__device__ __forceinline__ void mma16816(float c[4], const uint32_t a[4],
                                         uint32_t b0, uint32_t b1) {
    asm volatile("mma.sync.aligned.m16n8k16.row.col.f32.bf16.bf16.f32 "
                 "{%0,%1,%2,%3}, {%4,%5,%6,%7}, {%8,%9}, {%0,%1,%2,%3};"
                 : "+f"(c[0]), "+f"(c[1]), "+f"(c[2]), "+f"(c[3])
                 : "r"(a[0]), "r"(a[1]), "r"(a[2]), "r"(a[3]), "r"(b0), "r"(b1));
}
__device__ __forceinline__ void cp16(uint32_t saddr, const void* g) {
    asm volatile("cp.async.cg.shared.global [%0], [%1], 16;" :: "r"(saddr), "l"(g));
}
#define CP_COMMIT() asm volatile("cp.async.commit_group;" ::: "memory")

// RN split: fp32 pair -> packed bf16x2 hi (RN) + lo (RN of residual)
__device__ __forceinline__ void split2(float a, float b, uint32_t& hi, uint32_t& lo) {
    asm("cvt.rn.bf16x2.f32 %0, %1, %2;" : "=r"(hi) : "f"(b), "f"(a));
    float ha = __uint_as_float(hi << 16);
    float hb = __uint_as_float(hi & 0xffff0000u);
    float la = a - ha;
    float lb = b - hb;
    asm("cvt.rn.bf16x2.f32 %0, %1, %2;" : "=r"(lo) : "f"(lb), "f"(la));
}

// ---------------------------------------------------------------------------
// Prepass: split fp32 activation -> bf16 hi/lo
// ---------------------------------------------------------------------------
__global__ void split_act(const float* __restrict__ A, unsigned short* __restrict__ Ah,
                          unsigned short* __restrict__ Al, int n4)
{
    int idx = blockIdx.x * blockDim.x + threadIdx.x;
    if (idx >= n4) return;
    float4 v = reinterpret_cast<const float4*>(A)[idx];
    uint32_t h0, l0, h1, l1;
    split2(v.x, v.y, h0, l0);
    split2(v.z, v.w, h1, l1);
    *reinterpret_cast<uint2*>(Ah + (size_t)idx * 4) = make_uint2(h0, h1);
    *reinterpret_cast<uint2*>(Al + (size_t)idx * 4) = make_uint2(l0, l1);
}

// ---------------------------------------------------------------------------
// Prepass: transpose + split weights.  W[K,N] fp32 -> T[N,K] bf16 hi/lo.
// grid (N/32, K/32), block (32,8)
// ---------------------------------------------------------------------------
__global__ void transpose_split(const float* __restrict__ W, unsigned short* __restrict__ Th,
                                unsigned short* __restrict__ Tl, int K, int N)
{
    __shared__ float tile[32][33];
    const int tx = threadIdx.x, ty = threadIdx.y;
    const int n0 = blockIdx.x * 32, k0 = blockIdx.y * 32;
#pragma unroll
    for (int i = 0; i < 4; i++) {
        int kk = ty + 8 * i;
        tile[kk][tx] = W[(size_t)(k0 + kk) * N + n0 + tx];
    }
    __syncthreads();
    int tid = ty * 32 + tx;
    int nn  = tid >> 3;
    int kk4 = (tid & 7) * 4;
    float v0 = tile[kk4 + 0][nn], v1 = tile[kk4 + 1][nn];
    float v2 = tile[kk4 + 2][nn], v3 = tile[kk4 + 3][nn];
    uint32_t h0, l0, h1, l1;
    split2(v0, v1, h0, l0);
    split2(v2, v3, h1, l1);
    size_t o = (size_t)(n0 + nn) * K + k0 + kk4;
    *reinterpret_cast<uint2*>(Th + o) = make_uint2(h0, h1);
    *reinterpret_cast<uint2*>(Tl + o) = make_uint2(l0, l1);
}

// ---------------------------------------------------------------------------
// mma.sync GEMM:  C[M,N] = A[M,K] @ T[N,K]^T (+bias), 3-term bf16 split.
// CTA 128x128, BK=32, 3-stage cp.async pipeline, 256 threads (8 warps 2x4).
// smem stage (40960 B): Ah +0, Al +10240, Bh +20480, Bl +30720,
// each matrix 128 rows x 80 B (64 B data + 16 B pad -> ldmatrix conflict-free).
// ---------------------------------------------------------------------------
#define STAGE_B 40960
#define GEMM_SMEM (3 * STAGE_B)

__global__ __launch_bounds__(256, 1)
void gemm_tc(const unsigned short* __restrict__ Ah, const unsigned short* __restrict__ Al,
             const unsigned short* __restrict__ Bh, const unsigned short* __restrict__ Bl,
             const float* __restrict__ bias, float* __restrict__ C,
             int M, int N, int K)
{
    extern __shared__ __align__(128) char smem[];
    const uint32_t sb = (uint32_t)__cvta_generic_to_shared(smem);

    const int t    = threadIdx.x;
    const int lane = t & 31;
    const int wid  = t >> 5;
    const int wm   = (wid & 1) * 64;    // warp row offset
    const int wn   = (wid >> 1) * 32;   // warp col offset
    const int row0 = blockIdx.y * 128;
    const int col0 = blockIdx.x * 128;

    float c[4][4][4];
#pragma unroll
    for (int i = 0; i < 4; i++)
#pragma unroll
        for (int j = 0; j < 4; j++)
#pragma unroll
            for (int e = 0; e < 4; e++) c[i][j][e] = 0.f;

    const int nc = K >> 5;   // BK = 32

    auto stage = [&](int ch) {
        const uint32_t st = sb + (uint32_t)(ch % 3) * STAGE_B;
        const int kb = ch << 5;
#pragma unroll
        for (int q = 0; q < 8; q++) {
            int id  = t + q * 256;        // 0..2047
            int mat = id >> 9;            // 0:Ah 1:Al 2:Bh 3:Bl
            int w   = id & 511;
            int r   = w >> 2;             // row 0..127
            int c16 = w & 3;              // 16B chunk
            uint32_t so = st + (uint32_t)mat * 10240 + (uint32_t)(r * 80 + c16 * 16);
            const unsigned short* gp =
                (mat == 0) ? Ah + (size_t)(row0 + r) * K + kb + c16 * 8 :
                (mat == 1) ? Al + (size_t)(row0 + r) * K + kb + c16 * 8 :
                (mat == 2) ? Bh + (size_t)(col0 + r) * K + kb + c16 * 8 :
                             Bl + (size_t)(col0 + r) * K + kb + c16 * 8;
            cp16(so, gp);
        }
        CP_COMMIT();
    };

    stage(0);
    stage(1);

    // ldmatrix lane address components
    const int a_r  = lane & 15;            // A: rows 0..15
    const int a_c  = (lane >> 4) << 3;     // A: k offset 0/8
    const int b_m  = lane >> 3;            // B matrix idx 0..3
    const int b_r  = lane & 7;
    const int b_n  = ((b_m >> 1) << 3) + b_r;   // n row within 16
    const int b_k  = (b_m & 1) << 3;            // k offset 0/8

    for (int i = 0; i < nc; i++) {
        if (i + 2 < nc) asm volatile("cp.async.wait_group 1;" ::: "memory");
        else            asm volatile("cp.async.wait_group 0;" ::: "memory");
        __syncthreads();

        const uint32_t st = sb + (uint32_t)(i % 3) * STAGE_B;

#pragma unroll
        for (int ks = 0; ks < 2; ks++) {
            const int k0 = ks << 4;
            uint32_t ah[4][4], al4[4][4], bh[2][4], bl[2][4];
#pragma unroll
            for (int mi = 0; mi < 4; mi++) {
                uint32_t ar = st + (uint32_t)((wm + mi * 16 + a_r) * 80 + (k0 + a_c) * 2);
                ldm4(ah[mi],  ar);
                ldm4(al4[mi], ar + 10240);
            }
#pragma unroll
            for (int nh = 0; nh < 2; nh++) {
                uint32_t br = st + 20480 +
                    (uint32_t)((wn + nh * 16 + b_n) * 80 + (k0 + b_k) * 2);
                ldm4(bh[nh], br);
                ldm4(bl[nh], br + 10240);
            }
#pragma unroll
            for (int mi = 0; mi < 4; mi++)
#pragma unroll
                for (int ni = 0; ni < 4; ni++) {
                    uint32_t bh0 = bh[ni >> 1][(ni & 1) * 2];
                    uint32_t bh1 = bh[ni >> 1][(ni & 1) * 2 + 1];
                    uint32_t bl0 = bl[ni >> 1][(ni & 1) * 2];
                    uint32_t bl1 = bl[ni >> 1][(ni & 1) * 2 + 1];
                    mma16816(c[mi][ni], ah[mi],  bh0, bh1);
                    mma16816(c[mi][ni], al4[mi], bh0, bh1);
                    mma16816(c[mi][ni], ah[mi],  bl0, bl1);
                }
        }

        if (i + 2 < nc) stage(i + 2);
    }

    // Epilogue: m16n8 fragment -> rows lane/4 (+8), cols (lane%4)*2
#pragma unroll
    for (int mi = 0; mi < 4; mi++)
#pragma unroll
        for (int ni = 0; ni < 4; ni++) {
            int r   = row0 + wm + mi * 16 + (lane >> 2);
            int col = col0 + wn + ni * 8 + (lane & 3) * 2;
            float bx = bias ? bias[col]     : 0.f;
            float by = bias ? bias[col + 1] : 0.f;
            float2 v0 = make_float2(c[mi][ni][0] + bx, c[mi][ni][1] + by);
            float2 v1 = make_float2(c[mi][ni][2] + bx, c[mi][ni][3] + by);
            *reinterpret_cast<float2*>(C + (size_t)r * N + col)       = v0;
            *reinterpret_cast<float2*>(C + (size_t)(r + 8) * N + col) = v1;
        }
}

// ---------------------------------------------------------------------------
// RoPE (in-place)
// ---------------------------------------------------------------------------
__global__ void rope_kernel(float* __restrict__ buf,
                            const int* __restrict__ sidx, int nheads)
{
    int idx = blockIdx.x * blockDim.x + threadIdx.x;
    int total = MROWS * nheads * 64;
    if (idx >= total) return;
    int d   = idx & 63;
    int rem = idx >> 6;
    int h   = rem % nheads;
    int row = rem / nheads;
    int s   = row & (SEQ - 1);

    double pos = (double)sidx[s];
    double ang = pos * exp(-((double)d / 64.0) * 13.815510557964274);
    double sn, cs;
    sincos(ang, &sn, &cs);

    float* p = buf + (size_t)row * (nheads * 128) + h * 128 + d;
    float t1 = p[0];
    float t2 = p[64];
    p[0]  = t1 * (float)cs - t2 * (float)sn;
    p[64] = t2 * (float)cs + t1 * (float)sn;
}

// ---------------------------------------------------------------------------
// Flash attention (fp32, causal). BQ=64, BK=32, 256 threads.
// Epilogue emits split bf16 hi/lo for the Wo GEMM.
// ---------------------------------------------------------------------------
__global__ __launch_bounds__(256)
void attn_kernel(const float* __restrict__ Q, const float* __restrict__ Kc,
                 const float* __restrict__ Vc, const int* __restrict__ sidx,
                 unsigned short* __restrict__ Oh, unsigned short* __restrict__ Ol)
{
    __shared__ float4 Ks[32][32];
    __shared__ float4 Vs[32][32];
    __shared__ int    spos[32];

    const int t   = threadIdx.x;
    const int r   = t >> 2;
    const int sub = t & 3;
    const int b   = blockIdx.z;
    const int h   = blockIdx.y;
    const int q0  = blockIdx.x * 64;
    const int kvh = h >> 2;
    const int sq  = q0 + r;
    const int pos_q = sidx[sq];
    const float scale = 0.08838834764831845f;

    float4 qreg[8];
    {
        const float4* qp = reinterpret_cast<const float4*>(
            Q + (size_t)(b * SEQ + sq) * QCOLS + h * 128 + sub * 32);
#pragma unroll
        for (int c = 0; c < 8; c++) qreg[c] = qp[c];
    }

    float  m = -1e30f, l = 0.f;
    float4 acc[8];
#pragma unroll
    for (int c = 0; c < 8; c++) acc[c] = make_float4(0.f, 0.f, 0.f, 0.f);

    const float* Kbase = Kc + (size_t)b * SEQ * KCOLS + kvh * 128;
    const float* Vbase = Vc + (size_t)b * SEQ * KCOLS + kvh * 128;

    for (int k0 = 0; k0 < q0 + 64; k0 += 32) {
        __syncthreads();
#pragma unroll
        for (int w = 0; w < 4; w++) {
            int f  = w * 256 + t;
            int j  = f >> 5;
            int i4 = f & 31;
            Ks[j][i4] = *reinterpret_cast<const float4*>(
                Kbase + (size_t)(k0 + j) * KCOLS + i4 * 4);
            Vs[j][i4] = *reinterpret_cast<const float4*>(
                Vbase + (size_t)(k0 + j) * KCOLS + i4 * 4);
        }
        if (t < 32) spos[t] = sidx[k0 + t];
        __syncthreads();

        float sc[32];
        float tmax = -1e30f;
#pragma unroll
        for (int j = 0; j < 32; j++) {
            float s = 0.f;
#pragma unroll
            for (int c0 = 0; c0 < 8; c0++) {
                int c = (c0 + 2 * sub) & 7;
                float4 k4 = Ks[j][sub * 8 + c];
                float4 q4 = qreg[c];
                s += q4.x * k4.x + q4.y * k4.y + q4.z * k4.z + q4.w * k4.w;
            }
            s += __shfl_xor_sync(0xffffffffu, s, 1);
            s += __shfl_xor_sync(0xffffffffu, s, 2);
            s *= scale;
            if (spos[j] > pos_q) s = -1e30f;
            sc[j] = s;
            tmax = fmaxf(tmax, s);
        }

        float m_new = fmaxf(m, tmax);
        float corr  = __expf(m - m_new);
        l *= corr;
#pragma unroll
        for (int c = 0; c < 8; c++) {
            acc[c].x *= corr; acc[c].y *= corr;
            acc[c].z *= corr; acc[c].w *= corr;
        }
#pragma unroll
        for (int j = 0; j < 32; j++) {
            float p = __expf(sc[j] - m_new);
            l += p;
#pragma unroll
            for (int c0 = 0; c0 < 8; c0++) {
                int c = (c0 + 2 * sub) & 7;
                float4 v4 = Vs[j][sub * 8 + c];
                acc[c].x += p * v4.x; acc[c].y += p * v4.y;
                acc[c].z += p * v4.z; acc[c].w += p * v4.w;
            }
        }
        m = m_new;
    }

    float inv = 1.0f / l;
    size_t ob = (size_t)(b * SEQ + sq) * QCOLS + h * 128 + sub * 32;
#pragma unroll
    for (int c = 0; c < 8; c++) {
        float4 v = acc[c];
        v.x *= inv; v.y *= inv; v.z *= inv; v.w *= inv;
        uint32_t h0, l0, h1, l1;
        split2(v.x, v.y, h0, l0);
        split2(v.z, v.w, h1, l1);
        *reinterpret_cast<uint2*>(Oh + ob + c * 4) = make_uint2(h0, h1);
        *reinterpret_cast<uint2*>(Ol + ob + c * 4) = make_uint2(l0, l1);
    }
}

// ---------------------------------------------------------------------------
// Launch
// ---------------------------------------------------------------------------
extern "C" void kernel_launch(void* const* d_in, const int* in_sizes, int n_in,
                              void* d_out, int out_size)
{
    (void)in_sizes; (void)n_in; (void)out_size;
    const float* x    = (const float*)d_in[0];
    const int*   sidx = (const int*)  d_in[1];
    const float* Wq = (const float*)d_in[4];
    const float* bq = (const float*)d_in[5];
    const float* Wk = (const float*)d_in[6];
    const float* bk = (const float*)d_in[7];
    const float* Wv = (const float*)d_in[8];
    const float* bv = (const float*)d_in[9];
    const float* Wo = (const float*)d_in[10];
    float* out = (float*)d_out;

    float *pQ, *pK, *pV;
    cudaGetSymbolAddress((void**)&pQ, g_Q);
    cudaGetSymbolAddress((void**)&pK, g_K);
    cudaGetSymbolAddress((void**)&pV, g_V);
    unsigned short *xh, *xl, *aoh, *aol;
    unsigned short *wqh, *wql, *wkh, *wkl, *wvh, *wvl, *woh, *wol;
    cudaGetSymbolAddress((void**)&xh,  g_xh);
    cudaGetSymbolAddress((void**)&xl,  g_xl);
    cudaGetSymbolAddress((void**)&aoh, g_AOh);
    cudaGetSymbolAddress((void**)&aol, g_AOl);
    cudaGetSymbolAddress((void**)&wqh, g_Wqh);
    cudaGetSymbolAddress((void**)&wql, g_Wql);
    cudaGetSymbolAddress((void**)&wkh, g_Wkh);
    cudaGetSymbolAddress((void**)&wkl, g_Wkl);
    cudaGetSymbolAddress((void**)&wvh, g_Wvh);
    cudaGetSymbolAddress((void**)&wvl, g_Wvl);
    cudaGetSymbolAddress((void**)&woh, g_Woh);
    cudaGetSymbolAddress((void**)&wol, g_Wol);

    cudaFuncSetAttribute(gemm_tc, cudaFuncAttributeMaxDynamicSharedMemorySize, GEMM_SMEM);

    // Prepasses
    split_act<<<(MROWS * DMODEL / 4 + 255) / 256, 256>>>(x, xh, xl, MROWS * DMODEL / 4);
    transpose_split<<<dim3(QCOLS / 32, DMODEL / 32), dim3(32, 8)>>>(Wq, wqh, wql, DMODEL, QCOLS);
    transpose_split<<<dim3(KCOLS / 32, DMODEL / 32), dim3(32, 8)>>>(Wk, wkh, wkl, DMODEL, KCOLS);
    transpose_split<<<dim3(KCOLS / 32, DMODEL / 32), dim3(32, 8)>>>(Wv, wvh, wvl, DMODEL, KCOLS);
    transpose_split<<<dim3(QCOLS / 32, DMODEL / 32), dim3(32, 8)>>>(Wo, woh, wol, QCOLS, DMODEL);

    // QKV projections
    gemm_tc<<<dim3(QCOLS / 128, MROWS / 128), 256, GEMM_SMEM>>>(xh, xl, wqh, wql, bq, pQ, MROWS, QCOLS, DMODEL);
    gemm_tc<<<dim3(KCOLS / 128, MROWS / 128), 256, GEMM_SMEM>>>(xh, xl, wkh, wkl, bk, pK, MROWS, KCOLS, DMODEL);
    gemm_tc<<<dim3(KCOLS / 128, MROWS / 128), 256, GEMM_SMEM>>>(xh, xl, wvh, wvl, bv, pV, MROWS, KCOLS, DMODEL);

    // RoPE
    rope_kernel<<<(MROWS * NH   * 64 + 255) / 256, 256>>>(pQ, sidx, NH);
    rope_kernel<<<(MROWS * NKVH * 64 + 255) / 256, 256>>>(pK, sidx, NKVH);

    // Attention (emits split bf16)
    attn_kernel<<<dim3(SEQ / 64, NH, BSZ), 256>>>(pQ, pK, pV, sidx, aoh, aol);

    // Output projection
    gemm_tc<<<dim3(DMODEL / 128, MROWS / 128), 256, GEMM_SMEM>>>(aoh, aol, woh, wol, nullptr, out, MROWS, DMODEL, QCOLS);
}